// round 12
// baseline (speedup 1.0000x reference)
#include <cuda_runtime.h>
#include <cuda_fp16.h>
#include <cstdint>

// Problem constants
#define BATCH  4
#define SEQ    4096
#define M_TOK  (BATCH * SEQ)   // 16384 tokens
#define EDIM   1024
#define HEADS  16
#define DH     64
#define NTOT   3072            // packed N = q|k|v

typedef unsigned long long u64;
typedef unsigned int       u32;

// ---------------------------------------------------------------------------
// Device scratch (alloc-free per harness rules)
// A rows: [Xh(1024) | Xl(1024)] fp16 (residual unscaled; proven R10)
// B rows: [Wh(1024) | Wl(1024)]
// Cross-term partial sums (f16, packed half2 per u32), one array per K-parity.
// ---------------------------------------------------------------------------
__device__ __half g_a16[(size_t)M_TOK * 2048];
__device__ __half g_b16[(size_t)NTOT * 2048];
__device__ u32    g_c0[(size_t)M_TOK * NTOT / 2];
__device__ u32    g_c1[(size_t)M_TOK * NTOT / 2];
__device__ float  g_bias[NTOT];
__device__ float  g_qkv[(size_t)M_TOK * NTOT];   // q | k | v per row

// ---------------------------------------------------------------------------
// PTX helpers (compute_103-legal: cp.async / ldmatrix / mma.sync)
// ---------------------------------------------------------------------------
__device__ __forceinline__ u32 s2u(const void* p) {
    u32 a;
    asm("{ .reg .u64 t; cvta.to.shared.u64 t, %1; cvt.u32.u64 %0, t; }"
        : "=r"(a) : "l"(p));
    return a;
}
__device__ __forceinline__ void cpa16(u32 dst, const void* src) {
    asm volatile("cp.async.cg.shared.global [%0], [%1], 16;"
                 :: "r"(dst), "l"(src) : "memory");
}
#define CPA_COMMIT() asm volatile("cp.async.commit_group;" ::: "memory")
#define CPA_WAIT1()  asm volatile("cp.async.wait_group 1;" ::: "memory")

__device__ __forceinline__ void ldsm4(u32* r, u32 addr) {
    asm volatile("ldmatrix.sync.aligned.m8n8.x4.shared.b16 {%0,%1,%2,%3}, [%4];"
                 : "=r"(r[0]), "=r"(r[1]), "=r"(r[2]), "=r"(r[3]) : "r"(addr));
}
__device__ __forceinline__ void mma_h32(float* d, const u32* a, const u32* b) {
    asm volatile(
        "mma.sync.aligned.m16n8k16.row.col.f32.f16.f16.f32 "
        "{%0,%1,%2,%3}, {%4,%5,%6,%7}, {%8,%9}, {%0,%1,%2,%3};"
        : "+f"(d[0]), "+f"(d[1]), "+f"(d[2]), "+f"(d[3])
        : "r"(a[0]), "r"(a[1]), "r"(a[2]), "r"(a[3]), "r"(b[0]), "r"(b[1]));
}
__device__ __forceinline__ void mma_h16(u32* d, const u32* a, const u32* b) {
    asm volatile(
        "mma.sync.aligned.m16n8k16.row.col.f16.f16.f16.f16 "
        "{%0,%1}, {%2,%3,%4,%5}, {%6,%7}, {%0,%1};"
        : "+r"(d[0]), "+r"(d[1])
        : "r"(a[0]), "r"(a[1]), "r"(a[2]), "r"(a[3]), "r"(b[0]), "r"(b[1]));
}

// ---------------------------------------------------------------------------
// Pack kernels: fp16 hi + unscaled fp16 residual, [hi | lo] per row.
// ---------------------------------------------------------------------------
__device__ __forceinline__ void split16u(float4 v, __half2& h01, __half2& h23,
                                         __half2& l01, __half2& l23) {
    __half h0 = __float2half_rn(v.x);
    __half h1 = __float2half_rn(v.y);
    __half h2 = __float2half_rn(v.z);
    __half h3 = __float2half_rn(v.w);
    h01 = __halves2half2(h0, h1);
    h23 = __halves2half2(h2, h3);
    l01 = __halves2half2(__float2half_rn(v.x - __half2float(h0)),
                         __float2half_rn(v.y - __half2float(h1)));
    l23 = __halves2half2(__float2half_rn(v.z - __half2float(h2)),
                         __float2half_rn(v.w - __half2float(h3)));
}

__global__ void pack_a16(const float4* __restrict__ x) {
    int i = blockIdx.x * blockDim.x + threadIdx.x;
    const int n4 = M_TOK * EDIM / 4;
    const int stride = gridDim.x * blockDim.x;
    for (; i < n4; i += stride) {
        float4 v = x[i];
        __half2 h01, h23, l01, l23;
        split16u(v, h01, h23, l01, l23);
        const int e0  = i * 4;
        const int row = e0 >> 10;
        const int col = e0 & 1023;
        __half2* out = (__half2*)(g_a16 + (size_t)row * 2048);
        out[col >> 1]                = h01;
        out[(col >> 1) + 1]          = h23;
        out[(col + 1024) >> 1]       = l01;
        out[((col + 1024) >> 1) + 1] = l23;
    }
}

__global__ void pack_b16(const float4* __restrict__ Wq,
                         const float4* __restrict__ Wk,
                         const float4* __restrict__ Wv) {
    int i = blockIdx.x * blockDim.x + threadIdx.x;
    const int per = EDIM * EDIM / 4;
    const int n4 = 3 * per;
    const int stride = gridDim.x * blockDim.x;
    for (; i < n4; i += stride) {
        const int z = i / per;
        const int r = i - z * per;
        float4 v = (z == 0 ? Wq : z == 1 ? Wk : Wv)[r];
        __half2 h01, h23, l01, l23;
        split16u(v, h01, h23, l01, l23);
        const int e0  = r * 4;
        const int row = (e0 >> 10) + (z << 10);
        const int col = e0 & 1023;
        __half2* out = (__half2*)(g_b16 + (size_t)row * 2048);
        out[col >> 1]                = h01;
        out[(col >> 1) + 1]          = h23;
        out[(col + 1024) >> 1]       = l01;
        out[((col + 1024) >> 1) + 1] = l23;
    }
}

__global__ void pack_bias(const float* __restrict__ bq,
                          const float* __restrict__ bk,
                          const float* __restrict__ bv) {
    int i = blockIdx.x * blockDim.x + threadIdx.x;
    if (i < NTOT) {
        const int z = i >> 10;
        g_bias[i] = (z == 0 ? bq : z == 1 ? bk : bv)[i & 1023];
    }
}

// ---------------------------------------------------------------------------
// GEMM, 48 k-iterations, CTA 128x128, 8 warps, 3-stage cp.async, 2 CTAs/SM.
//   kt in [0,16):  cross term Xh*Wl  (f16 acc, 64x64 warp tiles, K-parity split)
//   kt in [16,32): cross term Xl*Wh  (same accumulators)
//   -> dump f16 accs to g_c0/g_c1 (L2-resident per-CTA spill)
//   kt in [32,48): main term Xh*Wh  (f32 acc, 64x32 warp tiles)
//   epilogue: main + cross(kpar0) + cross(kpar1) + bias -> g_qkv (fp32)
// ---------------------------------------------------------------------------
#define GBM 128
#define GBN 128
#define GBK 64
#define NSTG 3
#define KIT 48
#define X_IT 32
#define A_STG 16384               // 128 rows * 128B
#define B_STG 16384
#define STG_BYTES (A_STG + B_STG) // 32768
#define SMEM_GEMM (NSTG * STG_BYTES + 128)

__device__ __forceinline__ u32 swz(int row, int c) {
    return (u32)(row * 128 + ((c ^ (row & 7)) << 4));
}

// aptr/bptr: per-thread global bases (row tid>>3, chunk tid&7 pre-applied).
__device__ __forceinline__ void load_stage(u32 aB, u32 bB, int it,
                                           const __half* aptr, const __half* bptr,
                                           u32 dA) {
    // A chunk: Xh for cross-1 & main, Xl for cross-2
    const int ac = (it < X_IT) ? ((it < 16) ? it : it - 16 + ((it < X_IT && it >= 16) ? 0 : 0)) : it - X_IT;
    // note: cross-1 uses Xh chunks 0..15, cross-2 uses Xl chunks 16..31,
    // main uses Xh chunks 0..15. Simplify:
    const int ac2 = (it < 16) ? it : ((it < X_IT) ? (it - 16 + 16) : (it - X_IT));
    // B chunk: Wl for cross-1, Wh for cross-2 & main
    const int bc = (it < 16) ? it + 16 : ((it < X_IT) ? it - 16 : it - X_IT);
    (void)ac;
    const __half* as = aptr + ac2 * GBK;
    const __half* bs = bptr + bc * GBK;
    #pragma unroll
    for (int j = 0; j < 4; j++) {
        cpa16(aB + dA + j * (32 * 128), as + (size_t)j * 32 * 2048);
        cpa16(bB + dA + j * (32 * 128), bs + (size_t)j * 32 * 2048);
    }
}

__global__ void __launch_bounds__(256, 2)
qkv_mma_gemm()
{
    extern __shared__ char smraw[];
    const u32 smb = (s2u(smraw) + 127u) & ~127u;

    const int tid  = threadIdx.x;
    const int wid  = tid >> 5;
    const int lane = tid & 31;
    const int row0 = blockIdx.y * GBM;
    const int col0 = blockIdx.x * GBN;

    // cross-phase warp mapping: 2x2 grid of 64x64 tiles x 2 K-parities
    const int kpar = wid >> 2;         // 0: kk {0,2}, 1: kk {1,3}
    const int wmc  = (wid >> 1) & 1;   // 64-row half
    const int wnc  = wid & 1;          // 64-col half
    // main-phase warp mapping: 2x4 grid of 64x32 tiles
    const int wm   = wid & 1;
    const int wn   = wid >> 1;

    // per-thread cp.async source bases and swizzled dst offset
    const int lr = tid >> 3;           // 0..31
    const int lc = tid & 7;            // 16B chunk
    const __half* aptr = g_a16 + (size_t)(row0 + lr) * 2048 + lc * 8;
    const __half* bptr = g_b16 + (size_t)(col0 + lr) * 2048 + lc * 8;
    const u32 dA = swz(lr, lc);

    // prologue: stages 0,1
    load_stage(smb, smb + A_STG, 0, aptr, bptr, dA); CPA_COMMIT();
    load_stage(smb + STG_BYTES, smb + STG_BYTES + A_STG, 1, aptr, bptr, dA); CPA_COMMIT();

    // ================= cross phase (f16 acc, 64x64 tiles) =================
    u32 hacc[4][8][2];
    #pragma unroll
    for (int i = 0; i < 4; i++)
        #pragma unroll
        for (int j = 0; j < 8; j++) { hacc[i][j][0] = 0u; hacc[i][j][1] = 0u; }

    int slot = 0;
    for (int kt = 0; kt < X_IT; kt++) {
        CPA_WAIT1();
        __syncthreads();
        {
            int ns = slot + 2; if (ns >= NSTG) ns -= NSTG;
            const u32 nb = smb + ns * STG_BYTES;
            load_stage(nb, nb + A_STG, kt + 2, aptr, bptr, dA);
        }
        CPA_COMMIT();

        const u32 aB = smb + slot * STG_BYTES;
        const u32 bB = aB + A_STG;

        #pragma unroll
        for (int kh = 0; kh < 2; kh++) {
            const int kk = kpar + kh * 2;
            u32 ra[4][4];
            #pragma unroll
            for (int mi = 0; mi < 4; mi++) {
                const int r = wmc * 64 + mi * 16 + (lane & 15);
                const int c = kk * 2 + (lane >> 4);
                ldsm4(ra[mi], aB + swz(r, c));
            }
            u32 rb[4][4];
            #pragma unroll
            for (int ni = 0; ni < 4; ni++) {
                const int r = wnc * 64 + ni * 16 + (lane & 7) + ((lane >> 4) << 3);
                const int c = kk * 2 + ((lane >> 3) & 1);
                ldsm4(rb[ni], bB + swz(r, c));
            }
            #pragma unroll
            for (int mi = 0; mi < 4; mi++)
                #pragma unroll
                for (int n8 = 0; n8 < 8; n8++)
                    mma_h16(hacc[mi][n8], ra[mi], &rb[n8 >> 1][(n8 & 1) * 2]);
        }
        if (++slot == NSTG) slot = 0;
    }

    // ---- dump cross accs to global (per K-parity); frees registers ----
    {
        u32* dst = kpar ? g_c1 : g_c0;
        #pragma unroll
        for (int mi = 0; mi < 4; mi++) {
            const int r = row0 + wmc * 64 + mi * 16 + (lane >> 2);
            #pragma unroll
            for (int n8 = 0; n8 < 8; n8++) {
                const int c = col0 + wnc * 64 + n8 * 8 + (lane & 3) * 2;
                dst[(size_t)r * (NTOT / 2) + (c >> 1)]       = hacc[mi][n8][0];
                dst[(size_t)(r + 8) * (NTOT / 2) + (c >> 1)] = hacc[mi][n8][1];
            }
        }
    }

    // ================= main phase (f32 acc, 64x32 tiles) =================
    float acc[4][4][4];
    #pragma unroll
    for (int i = 0; i < 4; i++)
        #pragma unroll
        for (int j = 0; j < 4; j++)
            #pragma unroll
            for (int k = 0; k < 4; k++) acc[i][j][k] = 0.f;

    for (int kt = X_IT; kt < KIT; kt++) {
        CPA_WAIT1();
        __syncthreads();
        if (kt + 2 < KIT) {
            int ns = slot + 2; if (ns >= NSTG) ns -= NSTG;
            const u32 nb = smb + ns * STG_BYTES;
            load_stage(nb, nb + A_STG, kt + 2, aptr, bptr, dA);
        }
        CPA_COMMIT();

        const u32 aB = smb + slot * STG_BYTES;
        const u32 bB = aB + A_STG;

        #pragma unroll
        for (int kk = 0; kk < 4; kk++) {
            u32 ra[4][4];
            #pragma unroll
            for (int mi = 0; mi < 4; mi++) {
                const int r = wm * 64 + mi * 16 + (lane & 15);
                const int c = kk * 2 + (lane >> 4);
                ldsm4(ra[mi], aB + swz(r, c));
            }
            u32 rb[2][4];
            #pragma unroll
            for (int ni = 0; ni < 2; ni++) {
                const int r = wn * 32 + ni * 16 + (lane & 7) + ((lane >> 4) << 3);
                const int c = kk * 2 + ((lane >> 3) & 1);
                ldsm4(rb[ni], bB + swz(r, c));
            }
            #pragma unroll
            for (int mi = 0; mi < 4; mi++)
                #pragma unroll
                for (int n8 = 0; n8 < 4; n8++)
                    mma_h32(acc[mi][n8], ra[mi], &rb[n8 >> 1][(n8 & 1) * 2]);
        }
        if (++slot == NSTG) slot = 0;
    }

    // ---- epilogue: main + cross partials + bias -> g_qkv ----
    __syncthreads();   // order cross dumps (all warps) before cross reads
    const int rbase = row0 + wm * 64;
    const int cbase = col0 + wn * 32;
    #pragma unroll
    for (int mi = 0; mi < 4; mi++) {
        const int r = rbase + mi * 16 + (lane >> 2);
        #pragma unroll
        for (int n8 = 0; n8 < 4; n8++) {
            const int c = cbase + n8 * 8 + (lane & 3) * 2;
            const size_t i0 = (size_t)r * (NTOT / 2) + (c >> 1);
            const size_t i1 = (size_t)(r + 8) * (NTOT / 2) + (c >> 1);
            u32 u0 = __ldcg(&g_c0[i0]);
            u32 u1 = __ldcg(&g_c1[i0]);
            u32 u2 = __ldcg(&g_c0[i1]);
            u32 u3 = __ldcg(&g_c1[i1]);
            __half2 c00 = __hadd2(*(__half2*)&u0, *(__half2*)&u1);
            __half2 c01 = __hadd2(*(__half2*)&u2, *(__half2*)&u3);
            const float b0 = g_bias[c], b1 = g_bias[c + 1];
            float2 v0 = make_float2(acc[mi][n8][0] + __low2float(c00) + b0,
                                    acc[mi][n8][1] + __high2float(c00) + b1);
            float2 v1 = make_float2(acc[mi][n8][2] + __low2float(c01) + b0,
                                    acc[mi][n8][3] + __high2float(c01) + b1);
            *(float2*)&g_qkv[(size_t)r * NTOT + c]       = v0;
            *(float2*)&g_qkv[(size_t)(r + 8) * NTOT + c] = v1;
        }
    }
}

// ---------------------------------------------------------------------------
// Per-token head-head attention (proven; mask-before-softmax).
// ---------------------------------------------------------------------------
__global__ __launch_bounds__(128)
void attn_kernel(const float* __restrict__ mask, float* __restrict__ out)
{
    __shared__ float ks[4 * HEADS * DH];
    __shared__ float vs[4 * HEADS * DH];
    __shared__ float ms[HEADS * HEADS];

    const int tid = threadIdx.x;
    const size_t tok0 = (size_t)blockIdx.x * 4;

    for (int i = tid; i < HEADS * HEADS; i += 128) ms[i] = mask[i];

    float4* ks4 = (float4*)ks;
    float4* vs4 = (float4*)vs;
    #pragma unroll
    for (int tt = 0; tt < 4; tt++) {
        const float4* kg = (const float4*)(g_qkv + (tok0 + tt) * NTOT + EDIM);
        const float4* vg = (const float4*)(g_qkv + (tok0 + tt) * NTOT + 2 * EDIM);
        #pragma unroll
        for (int j = 0; j < 2; j++) {
            const int idx = tid + j * 128;
            ks4[tt * 256 + idx] = kg[idx];
            vs4[tt * 256 + idx] = vg[idx];
        }
    }
    __syncthreads();

    const int t    = tid >> 5;
    const int lane = tid & 31;
    const int h    = lane & 15;
    const int half = lane >> 4;

    float4 qv[8];
    const float4* qp = (const float4*)(g_qkv + (tok0 + t) * NTOT + h * DH + half * 32);
    #pragma unroll
    for (int i = 0; i < 8; i++) qv[i] = qp[i];

    float s[16];
    #pragma unroll
    for (int g = 0; g < 16; g++) {
        const float4* kr = (const float4*)(ks + (t * HEADS + g) * DH + half * 32);
        float ax = 0.f, ay = 0.f, az = 0.f, aw = 0.f;
        #pragma unroll
        for (int i = 0; i < 8; i++) {
            float4 kv = kr[i];
            ax += qv[i].x * kv.x; ay += qv[i].y * kv.y;
            az += qv[i].z * kv.z; aw += qv[i].w * kv.w;
        }
        float p = (ax + ay) + (az + aw);
        p += __shfl_xor_sync(0xFFFFFFFFu, p, 16);
        s[g] = p * ms[h * HEADS + g];
    }

    float m = s[0];
    #pragma unroll
    for (int g = 1; g < 16; g++) m = fmaxf(m, s[g]);
    float denom = 0.f;
    #pragma unroll
    for (int g = 0; g < 16; g++) { s[g] = expf(s[g] - m); denom += s[g]; }
    const float inv = 1.f / denom;

    float4 o[8];
    #pragma unroll
    for (int i = 0; i < 8; i++) o[i] = make_float4(0.f, 0.f, 0.f, 0.f);
    #pragma unroll
    for (int g = 0; g < 16; g++) {
        const float p = s[g] * inv;
        const float4* vr = (const float4*)(vs + (t * HEADS + g) * DH + half * 32);
        #pragma unroll
        for (int i = 0; i < 8; i++) {
            float4 vv = vr[i];
            o[i].x += p * vv.x; o[i].y += p * vv.y;
            o[i].z += p * vv.z; o[i].w += p * vv.w;
        }
    }

    float4* op = (float4*)(out + (tok0 + t) * EDIM + h * DH + half * 32);
    #pragma unroll
    for (int i = 0; i < 8; i++) op[i] = o[i];
}

// ---------------------------------------------------------------------------
// Launch. Inputs: x, sparsity_pattern, Wq, bq, Wk, bk, Wv, bv
// ---------------------------------------------------------------------------
extern "C" void kernel_launch(void* const* d_in, const int* in_sizes, int n_in,
                              void* d_out, int out_size)
{
    (void)in_sizes; (void)n_in; (void)out_size;
    const float* x  = (const float*)d_in[0];
    const float* sp = (const float*)d_in[1];
    const float* Wq = (const float*)d_in[2];
    const float* bq = (const float*)d_in[3];
    const float* Wk = (const float*)d_in[4];
    const float* bk = (const float*)d_in[5];
    const float* Wv = (const float*)d_in[6];
    const float* bv = (const float*)d_in[7];
    float* out = (float*)d_out;

    pack_a16<<<4096, 256>>>((const float4*)x);
    pack_b16<<<1536, 256>>>((const float4*)Wq, (const float4*)Wk, (const float4*)Wv);
    pack_bias<<<12, 256>>>(bq, bk, bv);

    cudaFuncSetAttribute(qkv_mma_gemm,
                         cudaFuncAttributeMaxDynamicSharedMemorySize, SMEM_GEMM);
    dim3 grid(NTOT / GBN, M_TOK / GBM);    // (24, 128)
    qkv_mma_gemm<<<grid, 256, SMEM_GEMM>>>();

    attn_kernel<<<M_TOK / 4, 128>>>(sp, out);
}

// round 13
// speedup vs baseline: 1.0664x; 1.0664x over previous
#include <cuda_runtime.h>
#include <cuda_fp16.h>
#include <cstdint>

// Problem constants
#define BATCH  4
#define SEQ    4096
#define M_TOK  (BATCH * SEQ)   // 16384 tokens
#define EDIM   1024
#define HEADS  16
#define DH     64
#define NTOT   3072            // packed N = q|k|v

typedef unsigned long long u64;
typedef unsigned int       u32;

// ---------------------------------------------------------------------------
// Device scratch (alloc-free per harness rules)
// A rows: [Xh(1024) | Xl(1024)]  fp16, residual UNSCALED (denormals OK on TC)
// B rows: [Wh(1024) | Wl(1024)]
// Terms: (hi,hi) + (hi,lo) + (lo,hi), all into one f32 accumulator.
// ---------------------------------------------------------------------------
__device__ __half g_a16[(size_t)M_TOK * 2048];
__device__ __half g_b16[(size_t)NTOT * 2048];
__device__ float  g_bias[NTOT];
__device__ float  g_qkv[(size_t)M_TOK * NTOT];   // q | k | v per row

// ---------------------------------------------------------------------------
// PTX helpers (compute_103-legal: cp.async / ldmatrix / mma.sync)
// ---------------------------------------------------------------------------
__device__ __forceinline__ u32 s2u(const void* p) {
    u32 a;
    asm("{ .reg .u64 t; cvta.to.shared.u64 t, %1; cvt.u32.u64 %0, t; }"
        : "=r"(a) : "l"(p));
    return a;
}
__device__ __forceinline__ void cpa16(u32 dst, const void* src) {
    asm volatile("cp.async.cg.shared.global [%0], [%1], 16;"
                 :: "r"(dst), "l"(src) : "memory");
}
#define CPA_COMMIT() asm volatile("cp.async.commit_group;" ::: "memory")
#define CPA_WAIT1()  asm volatile("cp.async.wait_group 1;" ::: "memory")

__device__ __forceinline__ void ldsm4(u32* r, u32 addr) {
    asm volatile("ldmatrix.sync.aligned.m8n8.x4.shared.b16 {%0,%1,%2,%3}, [%4];"
                 : "=r"(r[0]), "=r"(r[1]), "=r"(r[2]), "=r"(r[3]) : "r"(addr));
}
__device__ __forceinline__ void mma_h32(float* d, const u32* a, const u32* b) {
    asm volatile(
        "mma.sync.aligned.m16n8k16.row.col.f32.f16.f16.f32 "
        "{%0,%1,%2,%3}, {%4,%5,%6,%7}, {%8,%9}, {%0,%1,%2,%3};"
        : "+f"(d[0]), "+f"(d[1]), "+f"(d[2]), "+f"(d[3])
        : "r"(a[0]), "r"(a[1]), "r"(a[2]), "r"(a[3]), "r"(b[0]), "r"(b[1]));
}

// ---------------------------------------------------------------------------
// Pack kernels: fp16 hi + unscaled fp16 residual, [hi | lo] per row.
// ---------------------------------------------------------------------------
__device__ __forceinline__ void split16u(float4 v, __half2& h01, __half2& h23,
                                         __half2& l01, __half2& l23) {
    __half h0 = __float2half_rn(v.x);
    __half h1 = __float2half_rn(v.y);
    __half h2 = __float2half_rn(v.z);
    __half h3 = __float2half_rn(v.w);
    h01 = __halves2half2(h0, h1);
    h23 = __halves2half2(h2, h3);
    l01 = __halves2half2(__float2half_rn(v.x - __half2float(h0)),
                         __float2half_rn(v.y - __half2float(h1)));
    l23 = __halves2half2(__float2half_rn(v.z - __half2float(h2)),
                         __float2half_rn(v.w - __half2float(h3)));
}

__global__ void pack_a16(const float4* __restrict__ x) {
    int i = blockIdx.x * blockDim.x + threadIdx.x;
    const int n4 = M_TOK * EDIM / 4;
    const int stride = gridDim.x * blockDim.x;
    for (; i < n4; i += stride) {
        float4 v = x[i];
        __half2 h01, h23, l01, l23;
        split16u(v, h01, h23, l01, l23);
        const int e0  = i * 4;
        const int row = e0 >> 10;
        const int col = e0 & 1023;
        __half2* out = (__half2*)(g_a16 + (size_t)row * 2048);
        out[col >> 1]                = h01;
        out[(col >> 1) + 1]          = h23;
        out[(col + 1024) >> 1]       = l01;
        out[((col + 1024) >> 1) + 1] = l23;
    }
}

__global__ void pack_b16(const float4* __restrict__ Wq,
                         const float4* __restrict__ Wk,
                         const float4* __restrict__ Wv) {
    int i = blockIdx.x * blockDim.x + threadIdx.x;
    const int per = EDIM * EDIM / 4;
    const int n4 = 3 * per;
    const int stride = gridDim.x * blockDim.x;
    for (; i < n4; i += stride) {
        const int z = i / per;
        const int r = i - z * per;
        float4 v = (z == 0 ? Wq : z == 1 ? Wk : Wv)[r];
        __half2 h01, h23, l01, l23;
        split16u(v, h01, h23, l01, l23);
        const int e0  = r * 4;
        const int row = (e0 >> 10) + (z << 10);
        const int col = e0 & 1023;
        __half2* out = (__half2*)(g_b16 + (size_t)row * 2048);
        out[col >> 1]                = h01;
        out[(col >> 1) + 1]          = h23;
        out[(col + 1024) >> 1]       = l01;
        out[((col + 1024) >> 1) + 1] = l23;
    }
}

__global__ void pack_bias(const float* __restrict__ bq,
                          const float* __restrict__ bk,
                          const float* __restrict__ bv) {
    int i = blockIdx.x * blockDim.x + threadIdx.x;
    if (i < NTOT) {
        const int z = i >> 10;
        g_bias[i] = (z == 0 ? bq : z == 1 ? bk : bv)[i & 1023];
    }
}

// ---------------------------------------------------------------------------
// Unified fp16 GEMM, 48 iterations over one f32 accumulator (R10, proven):
//   kt in [0,16):  Xh * Wh      kt in [16,32): Xh * Wl      kt in [32,48): Xl * Wh
// CTA 128x128, 256 thr (8 warps, 64x32 tiles), 3-stage cp.async, 2 CTAs/SM.
// ---------------------------------------------------------------------------
#define GBM 128
#define GBN 128
#define GBK 64
#define NSTG 3
#define KIT 48
#define A_STG 16384               // 128 rows * 128B
#define B_STG 16384
#define STG_BYTES (A_STG + B_STG) // 32768
#define SMEM_GEMM (NSTG * STG_BYTES + 128)

__device__ __forceinline__ u32 swz(int row, int c) {
    return (u32)(row * 128 + ((c ^ (row & 7)) << 4));
}

// aptr/bptr: per-thread global base (row tid>>3, chunk tid&7 pre-applied).
__device__ __forceinline__ void load_stage(u32 aB, u32 bB, int it,
                                           const __half* aptr, const __half* bptr,
                                           u32 dA, u32 dB) {
    const int term = it >> 4;
    const int r16  = it & 15;
    const int ac = (term == 2) ? r16 + 16 : r16;   // A: lo only for term 2
    const int bc = (term == 1) ? r16 + 16 : r16;   // B: lo only for term 1
    const __half* as = aptr + ac * GBK;
    const __half* bs = bptr + bc * GBK;
    #pragma unroll
    for (int j = 0; j < 4; j++) {
        cpa16(aB + dA + j * (32 * 128), as + (size_t)j * 32 * 2048);
        cpa16(bB + dB + j * (32 * 128), bs + (size_t)j * 32 * 2048);
    }
}

__global__ void __launch_bounds__(256, 2)
qkv_mma_gemm()
{
    extern __shared__ char smraw[];
    const u32 smb = (s2u(smraw) + 127u) & ~127u;

    const int tid  = threadIdx.x;
    const int wid  = tid >> 5;
    const int lane = tid & 31;
    const int wm   = wid & 1;          // 0..1 -> 64 rows
    const int wn   = wid >> 1;         // 0..3 -> 32 cols
    const int row0 = blockIdx.y * GBM;
    const int col0 = blockIdx.x * GBN;

    // per-thread cp.async source bases and swizzled dst offsets
    const int lr = tid >> 3;           // 0..31 (row within 32-row group)
    const int lc = tid & 7;            // 16B chunk
    const __half* aptr = g_a16 + (size_t)(row0 + lr) * 2048 + lc * 8;
    const __half* bptr = g_b16 + (size_t)(col0 + lr) * 2048 + lc * 8;
    const u32 dA = swz(lr, lc);
    const u32 dB = swz(lr, lc);

    float acc[4][4][4];
    #pragma unroll
    for (int i = 0; i < 4; i++)
        #pragma unroll
        for (int j = 0; j < 4; j++)
            #pragma unroll
            for (int k = 0; k < 4; k++) acc[i][j][k] = 0.f;

    // prologue: stages 0,1
    load_stage(smb, smb + A_STG, 0, aptr, bptr, dA, dB); CPA_COMMIT();
    load_stage(smb + STG_BYTES, smb + STG_BYTES + A_STG, 1, aptr, bptr, dA, dB); CPA_COMMIT();

    #pragma unroll 3
    for (int kt = 0; kt < KIT; kt++) {
        const int slot = kt % NSTG;
        CPA_WAIT1();
        __syncthreads();

        // issue next stage immediately (that slot was last read pre-barrier)
        if (kt + 2 < KIT) {
            const int ns = (kt + 2) % NSTG;
            load_stage(smb + ns * STG_BYTES, smb + ns * STG_BYTES + A_STG,
                       kt + 2, aptr, bptr, dA, dB);
        }
        CPA_COMMIT();

        const u32 aB = smb + slot * STG_BYTES;
        const u32 bB = aB + A_STG;

        #pragma unroll
        for (int kk = 0; kk < 4; kk++) {
            u32 ra[4][4];
            #pragma unroll
            for (int mi = 0; mi < 4; mi++) {
                const int r = wm * 64 + mi * 16 + (lane & 15);
                const int c = kk * 2 + (lane >> 4);
                ldsm4(ra[mi], aB + swz(r, c));
            }
            u32 rb[2][4];
            #pragma unroll
            for (int ni = 0; ni < 2; ni++) {
                const int r = wn * 32 + ni * 16 + (lane & 7) + ((lane >> 4) << 3);
                const int c = kk * 2 + ((lane >> 3) & 1);
                ldsm4(rb[ni], bB + swz(r, c));
            }
            #pragma unroll
            for (int mi = 0; mi < 4; mi++)
                #pragma unroll
                for (int n8 = 0; n8 < 4; n8++)
                    mma_h32(acc[mi][n8], ra[mi], &rb[n8 >> 1][(n8 & 1) * 2]);
        }
    }

    // epilogue: add bias, write g_qkv
    const int rbase = row0 + wm * 64;
    const int cbase = col0 + wn * 32;
    #pragma unroll
    for (int mi = 0; mi < 4; mi++) {
        const int r = rbase + mi * 16 + (lane >> 2);
        #pragma unroll
        for (int n8 = 0; n8 < 4; n8++) {
            const int c = cbase + n8 * 8 + (lane & 3) * 2;
            const float b0 = g_bias[c], b1 = g_bias[c + 1];
            float2 v0 = make_float2(acc[mi][n8][0] + b0, acc[mi][n8][1] + b1);
            float2 v1 = make_float2(acc[mi][n8][2] + b0, acc[mi][n8][3] + b1);
            *(float2*)&g_qkv[(size_t)r * NTOT + c]       = v0;
            *(float2*)&g_qkv[(size_t)(r + 8) * NTOT + c] = v1;
        }
    }
}

// ---------------------------------------------------------------------------
// Per-token head-head attention — smem-free version.
// 128 threads / 4 tokens per block; 32 threads per token = (head, D-half).
// k/v rows are consumed once and shared by 16 head-threads reading IDENTICAL
// addresses -> L1 broadcast makes smem staging pointless; removing it lifts
// the smem occupancy cap (33KB -> 0) and kills the staging barrier.
// Mask-before-softmax semantics preserved.
// ---------------------------------------------------------------------------
__global__ __launch_bounds__(128)
void attn_kernel(const float* __restrict__ mask, float* __restrict__ out)
{
    const int tid  = threadIdx.x;
    const size_t tok0 = (size_t)blockIdx.x * 4;
    const int t    = tid >> 5;       // token (one warp per token)
    const int lane = tid & 31;
    const int h    = lane & 15;      // head
    const int half = lane >> 4;      // D-half

    const float* base = g_qkv + (tok0 + t) * NTOT;

    // q half-row into registers (8 float4 = 32 floats)
    float4 qv[8];
    const float4* qp = (const float4*)(base + h * DH + half * 32);
    #pragma unroll
    for (int i = 0; i < 8; i++) qv[i] = __ldg(qp + i);

    // scores: stream k rows (L1-broadcast across head-threads)
    float s[16];
    #pragma unroll
    for (int g = 0; g < 16; g++) {
        const float4* kr = (const float4*)(base + EDIM + g * DH + half * 32);
        float ax = 0.f, ay = 0.f, az = 0.f, aw = 0.f;
        #pragma unroll
        for (int i = 0; i < 8; i++) {
            float4 kv = __ldg(kr + i);
            ax += qv[i].x * kv.x; ay += qv[i].y * kv.y;
            az += qv[i].z * kv.z; aw += qv[i].w * kv.w;
        }
        float p = (ax + ay) + (az + aw);
        p += __shfl_xor_sync(0xFFFFFFFFu, p, 16);
        s[g] = p * __ldg(mask + h * HEADS + g);
    }

    // softmax over g (masked-to-zero entries included, like the reference)
    float m = s[0];
    #pragma unroll
    for (int g = 1; g < 16; g++) m = fmaxf(m, s[g]);
    float denom = 0.f;
    #pragma unroll
    for (int g = 0; g < 16; g++) { s[g] = expf(s[g] - m); denom += s[g]; }
    const float inv = 1.f / denom;

    // out half-row = sum_g p_g * v[g][half]  (stream v rows once)
    float4 o[8];
    #pragma unroll
    for (int i = 0; i < 8; i++) o[i] = make_float4(0.f, 0.f, 0.f, 0.f);
    #pragma unroll
    for (int g = 0; g < 16; g++) {
        const float p = s[g] * inv;
        const float4* vr = (const float4*)(base + 2 * EDIM + g * DH + half * 32);
        #pragma unroll
        for (int i = 0; i < 8; i++) {
            float4 vv = __ldg(vr + i);
            o[i].x += p * vv.x; o[i].y += p * vv.y;
            o[i].z += p * vv.z; o[i].w += p * vv.w;
        }
    }

    float4* op = (float4*)(out + (tok0 + t) * EDIM + h * DH + half * 32);
    #pragma unroll
    for (int i = 0; i < 8; i++) op[i] = o[i];
}

// ---------------------------------------------------------------------------
// Launch. Inputs: x, sparsity_pattern, Wq, bq, Wk, bk, Wv, bv
// ---------------------------------------------------------------------------
extern "C" void kernel_launch(void* const* d_in, const int* in_sizes, int n_in,
                              void* d_out, int out_size)
{
    (void)in_sizes; (void)n_in; (void)out_size;
    const float* x  = (const float*)d_in[0];
    const float* sp = (const float*)d_in[1];
    const float* Wq = (const float*)d_in[2];
    const float* bq = (const float*)d_in[3];
    const float* Wk = (const float*)d_in[4];
    const float* bk = (const float*)d_in[5];
    const float* Wv = (const float*)d_in[6];
    const float* bv = (const float*)d_in[7];
    float* out = (float*)d_out;

    pack_a16<<<4096, 256>>>((const float4*)x);
    pack_b16<<<1536, 256>>>((const float4*)Wq, (const float4*)Wk, (const float4*)Wv);
    pack_bias<<<12, 256>>>(bq, bk, bv);

    cudaFuncSetAttribute(qkv_mma_gemm,
                         cudaFuncAttributeMaxDynamicSharedMemorySize, SMEM_GEMM);
    dim3 grid(NTOT / GBN, M_TOK / GBM);    // (24, 128)
    qkv_mma_gemm<<<grid, 256, SMEM_GEMM>>>();

    attn_kernel<<<M_TOK / 4, 128>>>(sp, out);
}

// round 14
// speedup vs baseline: 1.1288x; 1.0585x over previous
#include <cuda_runtime.h>
#include <cuda_fp16.h>
#include <cstdint>

// Problem constants
#define BATCH  4
#define SEQ    4096
#define M_TOK  (BATCH * SEQ)   // 16384 tokens
#define EDIM   1024
#define HEADS  16
#define DH     64
#define NTOT   3072            // packed N = q|k|v

typedef unsigned long long u64;
typedef unsigned int       u32;

// ---------------------------------------------------------------------------
// Device scratch (alloc-free per harness rules)
// A rows: [Xh(1024) | Xl(1024)]  fp16, residual UNSCALED (denormals OK on TC)
// B rows: [Wh(1024) | Wl(1024)]
// Terms: (hi,hi) + (hi,lo) + (lo,hi), all into one f32 accumulator.
// ---------------------------------------------------------------------------
__device__ __half g_a16[(size_t)M_TOK * 2048];
__device__ __half g_b16[(size_t)NTOT * 2048];
__device__ float  g_bias[NTOT];
__device__ float  g_qkv[(size_t)M_TOK * NTOT];   // q | k | v per row

// ---------------------------------------------------------------------------
// PTX helpers (compute_103-legal: cp.async / ldmatrix / mma.sync)
// ---------------------------------------------------------------------------
__device__ __forceinline__ u32 s2u(const void* p) {
    u32 a;
    asm("{ .reg .u64 t; cvta.to.shared.u64 t, %1; cvt.u32.u64 %0, t; }"
        : "=r"(a) : "l"(p));
    return a;
}
__device__ __forceinline__ void cpa16(u32 dst, const void* src) {
    asm volatile("cp.async.cg.shared.global [%0], [%1], 16;"
                 :: "r"(dst), "l"(src) : "memory");
}
#define CPA_COMMIT() asm volatile("cp.async.commit_group;" ::: "memory")
#define CPA_WAIT1()  asm volatile("cp.async.wait_group 1;" ::: "memory")

__device__ __forceinline__ void ldsm4(u32* r, u32 addr) {
    asm volatile("ldmatrix.sync.aligned.m8n8.x4.shared.b16 {%0,%1,%2,%3}, [%4];"
                 : "=r"(r[0]), "=r"(r[1]), "=r"(r[2]), "=r"(r[3]) : "r"(addr));
}
__device__ __forceinline__ void mma_h32(float* d, const u32* a, const u32* b) {
    asm volatile(
        "mma.sync.aligned.m16n8k16.row.col.f32.f16.f16.f32 "
        "{%0,%1,%2,%3}, {%4,%5,%6,%7}, {%8,%9}, {%0,%1,%2,%3};"
        : "+f"(d[0]), "+f"(d[1]), "+f"(d[2]), "+f"(d[3])
        : "r"(a[0]), "r"(a[1]), "r"(a[2]), "r"(a[3]), "r"(b[0]), "r"(b[1]));
}

// ---------------------------------------------------------------------------
// Pack: fp16 hi + unscaled fp16 residual, [hi(1024) | lo(1024)] per row.
// Vectorized: 8 floats per thread -> one 16B hi store + one 16B lo store.
// ---------------------------------------------------------------------------
__device__ __forceinline__ void split8(float4 v0, float4 v1, uint4& hi, uint4& lo) {
    float f[8] = {v0.x, v0.y, v0.z, v0.w, v1.x, v1.y, v1.z, v1.w};
    u32 hw[4], lw[4];
    #pragma unroll
    for (int j = 0; j < 4; j++) {
        __half ha = __float2half_rn(f[2 * j]);
        __half hb = __float2half_rn(f[2 * j + 1]);
        __half2 hh = __halves2half2(ha, hb);
        __half2 ll = __halves2half2(
            __float2half_rn(f[2 * j]     - __half2float(ha)),
            __float2half_rn(f[2 * j + 1] - __half2float(hb)));
        hw[j] = *(u32*)&hh;
        lw[j] = *(u32*)&ll;
    }
    hi = make_uint4(hw[0], hw[1], hw[2], hw[3]);
    lo = make_uint4(lw[0], lw[1], lw[2], lw[3]);
}

__global__ void pack_a16(const float4* __restrict__ x) {
    const int i = blockIdx.x * blockDim.x + threadIdx.x;   // 8-float group id
    // n8 = M_TOK*EDIM/8 = 2097152; grid sized exactly
    float4 v0 = x[2 * i], v1 = x[2 * i + 1];
    uint4 hi, lo;
    split8(v0, v1, hi, lo);
    const int e0  = i * 8;
    const int row = e0 >> 10;
    const int col = e0 & 1023;
    __half* rbase = g_a16 + (size_t)row * 2048;
    *(uint4*)(rbase + col)        = hi;
    *(uint4*)(rbase + 1024 + col) = lo;
}

__global__ void pack_b16(const float4* __restrict__ Wq,
                         const float4* __restrict__ Wk,
                         const float4* __restrict__ Wv) {
    const int i = blockIdx.x * blockDim.x + threadIdx.x;   // 8-float group id
    const int per = EDIM * EDIM / 8;                       // 131072 per matrix
    const int z = i / per;
    const int r = i - z * per;
    const float4* src = (z == 0 ? Wq : z == 1 ? Wk : Wv);
    float4 v0 = src[2 * r], v1 = src[2 * r + 1];
    uint4 hi, lo;
    split8(v0, v1, hi, lo);
    const int e0  = r * 8;
    const int row = (e0 >> 10) + (z << 10);
    const int col = e0 & 1023;
    __half* rbase = g_b16 + (size_t)row * 2048;
    *(uint4*)(rbase + col)        = hi;
    *(uint4*)(rbase + 1024 + col) = lo;
}

__global__ void pack_bias(const float* __restrict__ bq,
                          const float* __restrict__ bk,
                          const float* __restrict__ bv) {
    int i = blockIdx.x * blockDim.x + threadIdx.x;
    if (i < NTOT) {
        const int z = i >> 10;
        g_bias[i] = (z == 0 ? bq : z == 1 ? bk : bv)[i & 1023];
    }
}

// ---------------------------------------------------------------------------
// Unified fp16 GEMM, 48 iterations over one f32 accumulator (R10, proven):
//   kt in [0,16):  Xh * Wh      kt in [16,32): Xh * Wl      kt in [32,48): Xl * Wh
// CTA 128x128, 256 thr (8 warps, 64x32 tiles), 3-stage cp.async, 2 CTAs/SM.
// ---------------------------------------------------------------------------
#define GBM 128
#define GBN 128
#define GBK 64
#define NSTG 3
#define KIT 48
#define A_STG 16384               // 128 rows * 128B
#define B_STG 16384
#define STG_BYTES (A_STG + B_STG) // 32768
#define SMEM_GEMM (NSTG * STG_BYTES + 128)

__device__ __forceinline__ u32 swz(int row, int c) {
    return (u32)(row * 128 + ((c ^ (row & 7)) << 4));
}

// aptr/bptr: per-thread global base (row tid>>3, chunk tid&7 pre-applied).
__device__ __forceinline__ void load_stage(u32 aB, u32 bB, int it,
                                           const __half* aptr, const __half* bptr,
                                           u32 dA, u32 dB) {
    const int term = it >> 4;
    const int r16  = it & 15;
    const int ac = (term == 2) ? r16 + 16 : r16;   // A: lo only for term 2
    const int bc = (term == 1) ? r16 + 16 : r16;   // B: lo only for term 1
    const __half* as = aptr + ac * GBK;
    const __half* bs = bptr + bc * GBK;
    #pragma unroll
    for (int j = 0; j < 4; j++) {
        cpa16(aB + dA + j * (32 * 128), as + (size_t)j * 32 * 2048);
        cpa16(bB + dB + j * (32 * 128), bs + (size_t)j * 32 * 2048);
    }
}

__global__ void __launch_bounds__(256, 2)
qkv_mma_gemm()
{
    extern __shared__ char smraw[];
    const u32 smb = (s2u(smraw) + 127u) & ~127u;

    const int tid  = threadIdx.x;
    const int wid  = tid >> 5;
    const int lane = tid & 31;
    const int wm   = wid & 1;          // 0..1 -> 64 rows
    const int wn   = wid >> 1;         // 0..3 -> 32 cols
    const int row0 = blockIdx.y * GBM;
    const int col0 = blockIdx.x * GBN;

    // per-thread cp.async source bases and swizzled dst offsets
    const int lr = tid >> 3;           // 0..31 (row within 32-row group)
    const int lc = tid & 7;            // 16B chunk
    const __half* aptr = g_a16 + (size_t)(row0 + lr) * 2048 + lc * 8;
    const __half* bptr = g_b16 + (size_t)(col0 + lr) * 2048 + lc * 8;
    const u32 dA = swz(lr, lc);
    const u32 dB = swz(lr, lc);

    float acc[4][4][4];
    #pragma unroll
    for (int i = 0; i < 4; i++)
        #pragma unroll
        for (int j = 0; j < 4; j++)
            #pragma unroll
            for (int k = 0; k < 4; k++) acc[i][j][k] = 0.f;

    // prologue: stages 0,1
    load_stage(smb, smb + A_STG, 0, aptr, bptr, dA, dB); CPA_COMMIT();
    load_stage(smb + STG_BYTES, smb + STG_BYTES + A_STG, 1, aptr, bptr, dA, dB); CPA_COMMIT();

    #pragma unroll 3
    for (int kt = 0; kt < KIT; kt++) {
        const int slot = kt % NSTG;
        CPA_WAIT1();
        __syncthreads();

        // issue next stage immediately (that slot was last read pre-barrier)
        if (kt + 2 < KIT) {
            const int ns = (kt + 2) % NSTG;
            load_stage(smb + ns * STG_BYTES, smb + ns * STG_BYTES + A_STG,
                       kt + 2, aptr, bptr, dA, dB);
        }
        CPA_COMMIT();

        const u32 aB = smb + slot * STG_BYTES;
        const u32 bB = aB + A_STG;

        #pragma unroll
        for (int kk = 0; kk < 4; kk++) {
            u32 ra[4][4];
            #pragma unroll
            for (int mi = 0; mi < 4; mi++) {
                const int r = wm * 64 + mi * 16 + (lane & 15);
                const int c = kk * 2 + (lane >> 4);
                ldsm4(ra[mi], aB + swz(r, c));
            }
            u32 rb[2][4];
            #pragma unroll
            for (int ni = 0; ni < 2; ni++) {
                const int r = wn * 32 + ni * 16 + (lane & 7) + ((lane >> 4) << 3);
                const int c = kk * 2 + ((lane >> 3) & 1);
                ldsm4(rb[ni], bB + swz(r, c));
            }
            #pragma unroll
            for (int mi = 0; mi < 4; mi++)
                #pragma unroll
                for (int n8 = 0; n8 < 4; n8++)
                    mma_h32(acc[mi][n8], ra[mi], &rb[n8 >> 1][(n8 & 1) * 2]);
        }
    }

    // epilogue: add bias, write g_qkv
    const int rbase = row0 + wm * 64;
    const int cbase = col0 + wn * 32;
    #pragma unroll
    for (int mi = 0; mi < 4; mi++) {
        const int r = rbase + mi * 16 + (lane >> 2);
        #pragma unroll
        for (int n8 = 0; n8 < 4; n8++) {
            const int c = cbase + n8 * 8 + (lane & 3) * 2;
            const float b0 = g_bias[c], b1 = g_bias[c + 1];
            float2 v0 = make_float2(acc[mi][n8][0] + b0, acc[mi][n8][1] + b1);
            float2 v1 = make_float2(acc[mi][n8][2] + b0, acc[mi][n8][3] + b1);
            *(float2*)&g_qkv[(size_t)r * NTOT + c]       = v0;
            *(float2*)&g_qkv[(size_t)(r + 8) * NTOT + c] = v1;
        }
    }
}

// ---------------------------------------------------------------------------
// Per-token head-head attention (R10 smem version, proven 46us).
// 128 threads / 4 tokens per block; 32 threads per token = (head, D-half).
// Mask-before-softmax semantics.
// ---------------------------------------------------------------------------
__global__ __launch_bounds__(128)
void attn_kernel(const float* __restrict__ mask, float* __restrict__ out)
{
    __shared__ float ks[4 * HEADS * DH];
    __shared__ float vs[4 * HEADS * DH];
    __shared__ float ms[HEADS * HEADS];

    const int tid = threadIdx.x;
    const size_t tok0 = (size_t)blockIdx.x * 4;

    for (int i = tid; i < HEADS * HEADS; i += 128) ms[i] = mask[i];

    float4* ks4 = (float4*)ks;
    float4* vs4 = (float4*)vs;
    #pragma unroll
    for (int tt = 0; tt < 4; tt++) {
        const float4* kg = (const float4*)(g_qkv + (tok0 + tt) * NTOT + EDIM);
        const float4* vg = (const float4*)(g_qkv + (tok0 + tt) * NTOT + 2 * EDIM);
        #pragma unroll
        for (int j = 0; j < 2; j++) {
            const int idx = tid + j * 128;
            ks4[tt * 256 + idx] = kg[idx];
            vs4[tt * 256 + idx] = vg[idx];
        }
    }
    __syncthreads();

    const int t    = tid >> 5;
    const int lane = tid & 31;
    const int h    = lane & 15;
    const int half = lane >> 4;

    float4 qv[8];
    const float4* qp = (const float4*)(g_qkv + (tok0 + t) * NTOT + h * DH + half * 32);
    #pragma unroll
    for (int i = 0; i < 8; i++) qv[i] = qp[i];

    float s[16];
    #pragma unroll
    for (int g = 0; g < 16; g++) {
        const float4* kr = (const float4*)(ks + (t * HEADS + g) * DH + half * 32);
        float ax = 0.f, ay = 0.f, az = 0.f, aw = 0.f;
        #pragma unroll
        for (int i = 0; i < 8; i++) {
            float4 kv = kr[i];
            ax += qv[i].x * kv.x; ay += qv[i].y * kv.y;
            az += qv[i].z * kv.z; aw += qv[i].w * kv.w;
        }
        float p = (ax + ay) + (az + aw);
        p += __shfl_xor_sync(0xFFFFFFFFu, p, 16);
        s[g] = p * ms[h * HEADS + g];
    }

    float m = s[0];
    #pragma unroll
    for (int g = 1; g < 16; g++) m = fmaxf(m, s[g]);
    float denom = 0.f;
    #pragma unroll
    for (int g = 0; g < 16; g++) { s[g] = expf(s[g] - m); denom += s[g]; }
    const float inv = 1.f / denom;

    float4 o[8];
    #pragma unroll
    for (int i = 0; i < 8; i++) o[i] = make_float4(0.f, 0.f, 0.f, 0.f);
    #pragma unroll
    for (int g = 0; g < 16; g++) {
        const float p = s[g] * inv;
        const float4* vr = (const float4*)(vs + (t * HEADS + g) * DH + half * 32);
        #pragma unroll
        for (int i = 0; i < 8; i++) {
            float4 vv = vr[i];
            o[i].x += p * vv.x; o[i].y += p * vv.y;
            o[i].z += p * vv.z; o[i].w += p * vv.w;
        }
    }

    float4* op = (float4*)(out + (tok0 + t) * EDIM + h * DH + half * 32);
    #pragma unroll
    for (int i = 0; i < 8; i++) op[i] = o[i];
}

// ---------------------------------------------------------------------------
// Launch. Inputs: x, sparsity_pattern, Wq, bq, Wk, bk, Wv, bv
// ---------------------------------------------------------------------------
extern "C" void kernel_launch(void* const* d_in, const int* in_sizes, int n_in,
                              void* d_out, int out_size)
{
    (void)in_sizes; (void)n_in; (void)out_size;
    const float* x  = (const float*)d_in[0];
    const float* sp = (const float*)d_in[1];
    const float* Wq = (const float*)d_in[2];
    const float* bq = (const float*)d_in[3];
    const float* Wk = (const float*)d_in[4];
    const float* bk = (const float*)d_in[5];
    const float* Wv = (const float*)d_in[6];
    const float* bv = (const float*)d_in[7];
    float* out = (float*)d_out;

    pack_a16<<<(M_TOK * EDIM / 8) / 256, 256>>>((const float4*)x);      // 8192 blocks
    pack_b16<<<(3 * EDIM * EDIM / 8) / 256, 256>>>((const float4*)Wq,
                                                   (const float4*)Wk,
                                                   (const float4*)Wv);  // 1536 blocks
    pack_bias<<<12, 256>>>(bq, bk, bv);

    cudaFuncSetAttribute(qkv_mma_gemm,
                         cudaFuncAttributeMaxDynamicSharedMemorySize, SMEM_GEMM);
    dim3 grid(NTOT / GBN, M_TOK / GBM);    // (24, 128)
    qkv_mma_gemm<<<grid, 256, SMEM_GEMM>>>();

    attn_kernel<<<M_TOK / 4, 128>>>(sp, out);
}